// round 2
// baseline (speedup 1.0000x reference)
#include <cuda_runtime.h>
#include <math.h>

// dims
#define E    256
#define H    128
#define NQ   8
#define QED  64
#define HEADS 2
#define HYP  64
#define NA   14
#define NAG  8
#define BEP  512
#define BS   4096          // BEP*NAG
#define BSG  512           // BS/NAG
#define WSZ  32768         // H*H*HEADS

// output layout: sorted_q [BS,NA,NQ] | h [BS,H] | rq [BSG,NQ]
#define OFF_SQ 0
#define OFF_H  (BS*NA*NQ)            // 458752
#define OFF_RQ (OFF_H + BS*H)        // 983040

// scratch (device globals; no allocation allowed)
__device__ __align__(16) float g_hh[HYP];
__device__ __align__(16) float g_msm[2*H];
__device__ __align__(16) float g_W[H*2*H];        // [128][256]
__device__ __align__(16) float g_wiT[H*3*H];      // [k][o] 128x384
__device__ __align__(16) float g_whT[H*3*H];
__device__ __align__(16) float g_h[BS*H];
__device__ __align__(16) float g_qphi[BSG*NQ*H];

// ---------------------------------------------------------------------------
// prep: hh = relu(colsum(hyp_w1)+b1); merger softmax over heads
__global__ void k_prep(const float* __restrict__ hyp_w1,
                       const float* __restrict__ hyp_b1,
                       const float* __restrict__ merger_w) {
    int t = threadIdx.x;
    if (t < HYP) {
        float s = hyp_b1[t];
        #pragma unroll
        for (int q = 0; q < NQ; q++) s += hyp_w1[q*HYP + t];
        g_hh[t] = fmaxf(s, 0.f);
    }
    if (t < H) {
        float a = merger_w[t], b = merger_w[H + t];
        float m = fmaxf(a, b);
        float e0 = expf(a - m), e1 = expf(b - m);
        float inv = 1.f / (e0 + e1);
        g_msm[t]     = e0 * inv;
        g_msm[H + t] = e1 * inv;
    }
}

// ---------------------------------------------------------------------------
// W[m] = sum_f hh[f]*hyp_w2[f*WSZ+m] + hyp_b2[m]   (m = i*256 + o)
__global__ void k_buildW(const float* __restrict__ hyp_w2,
                         const float* __restrict__ hyp_b2) {
    __shared__ float sh[HYP];
    int t = threadIdx.x;
    if (t < HYP) sh[t] = g_hh[t];
    __syncthreads();
    int m = blockIdx.x * blockDim.x + t;
    float acc = hyp_b2[m];
    #pragma unroll 8
    for (int f = 0; f < HYP; f++) acc = fmaf(sh[f], hyp_w2[f*WSZ + m], acc);
    g_W[m] = acc;
}

// ---------------------------------------------------------------------------
// transpose gru weights: wiT[k*384+o] = gru_wi[o*128+k]
__global__ void k_transpose(const float* __restrict__ gwi,
                            const float* __restrict__ gwh) {
    int idx = blockIdx.x * blockDim.x + threadIdx.x;   // 0..49151
    int o = idx >> 7, k = idx & 127;
    g_wiT[k*(3*H) + o] = gwi[idx];
    g_whT[k*(3*H) + o] = gwh[idx];
}

// ---------------------------------------------------------------------------
// main fused: fc1 -> emb (x@W) -> merge -> GRU ; 32 rows per block
__global__ __launch_bounds__(256)
void k_main(const float* __restrict__ in, const float* __restrict__ hprev,
            const float* __restrict__ fc1_w, const float* __restrict__ fc1_b,
            const float* __restrict__ gbi,  const float* __restrict__ gbh,
            float* __restrict__ out) {
    __shared__ float sA[32*256];   // input rows; later holds hprev tile (first 4096)
    __shared__ float sX[32*128];   // x, then x2
    const int tid = threadIdx.x;
    const int row0 = blockIdx.x * 32;

    for (int i = tid; i < 32*256; i += 256) sA[i] = in[row0*E + i];
    __syncthreads();

    const int rg = tid >> 5;        // 0..7
    const int cg = tid & 31;        // 0..31
    const int r0 = rg * 4;
    const int c0 = cg * 4;

    // ---- GEMM1: x = relu(A[32,256] @ fc1_w[256,128] + b) ----
    {
        float acc[4][4] = {};
        const float* Bp = fc1_w + c0;
        #pragma unroll 4
        for (int k = 0; k < E; k++) {
            float4 b = *(const float4*)(Bp + k*H);
            float a0 = sA[(r0+0)*E + k];
            float a1 = sA[(r0+1)*E + k];
            float a2 = sA[(r0+2)*E + k];
            float a3 = sA[(r0+3)*E + k];
            const float* bp = &b.x;
            #pragma unroll
            for (int c = 0; c < 4; c++) {
                acc[0][c] = fmaf(a0, bp[c], acc[0][c]);
                acc[1][c] = fmaf(a1, bp[c], acc[1][c]);
                acc[2][c] = fmaf(a2, bp[c], acc[2][c]);
                acc[3][c] = fmaf(a3, bp[c], acc[3][c]);
            }
        }
        float4 bias = *(const float4*)(fc1_b + c0);
        const float* bb = &bias.x;
        #pragma unroll
        for (int r = 0; r < 4; r++)
            #pragma unroll
            for (int c = 0; c < 4; c++)
                sX[(r0+r)*H + c0 + c] = fmaxf(acc[r][c] + bb[c], 0.f);
    }
    __syncthreads();

    // ---- GEMM2: e = x @ W[128,256]; cols c0..c0+3 (head0) and 128+c0.. (head1) ----
    float e0a[4][4] = {}, e1a[4][4] = {};
    {
        #pragma unroll 2
        for (int k = 0; k < H; k++) {
            float4 b0 = *(const float4*)(g_W + k*(2*H) + c0);
            float4 b1 = *(const float4*)(g_W + k*(2*H) + H + c0);
            const float* b0p = &b0.x; const float* b1p = &b1.x;
            float a0 = sX[(r0+0)*H + k];
            float a1 = sX[(r0+1)*H + k];
            float a2 = sX[(r0+2)*H + k];
            float a3 = sX[(r0+3)*H + k];
            #pragma unroll
            for (int c = 0; c < 4; c++) {
                e0a[0][c] = fmaf(a0, b0p[c], e0a[0][c]);
                e0a[1][c] = fmaf(a1, b0p[c], e0a[1][c]);
                e0a[2][c] = fmaf(a2, b0p[c], e0a[2][c]);
                e0a[3][c] = fmaf(a3, b0p[c], e0a[3][c]);
                e1a[0][c] = fmaf(a0, b1p[c], e1a[0][c]);
                e1a[1][c] = fmaf(a1, b1p[c], e1a[1][c]);
                e1a[2][c] = fmaf(a2, b1p[c], e1a[2][c]);
                e1a[3][c] = fmaf(a3, b1p[c], e1a[3][c]);
            }
        }
    }
    __syncthreads();   // all reads of sX(x) done; safe to overwrite with x2

    // ---- merge + relu -> x2 in sX; stage hprev tile into sA ----
    {
        float4 m0 = *(const float4*)(g_msm + c0);
        float4 m1 = *(const float4*)(g_msm + H + c0);
        const float* m0p = &m0.x; const float* m1p = &m1.x;
        #pragma unroll
        for (int r = 0; r < 4; r++)
            #pragma unroll
            for (int c = 0; c < 4; c++)
                sX[(r0+r)*H + c0 + c] =
                    fmaxf(m0p[c]*e0a[r][c] + m1p[c]*e1a[r][c], 0.f);
    }
    for (int i = tid; i < 32*H; i += 256) sA[i] = hprev[row0*H + i];
    __syncthreads();

    // ---- GRU: 6 dot-products per (row, j); in-register combine ----
    {
        const int j0 = c0;
        float aIr[4][4] = {}, aIz[4][4] = {}, aIn[4][4] = {};
        float aHr[4][4] = {}, aHz[4][4] = {}, aHn[4][4] = {};
        #pragma unroll 2
        for (int k = 0; k < H; k++) {
            float4 bir = *(const float4*)(g_wiT + k*(3*H) + j0);
            float4 biz = *(const float4*)(g_wiT + k*(3*H) + H + j0);
            float4 bin_ = *(const float4*)(g_wiT + k*(3*H) + 2*H + j0);
            float4 bhr = *(const float4*)(g_whT + k*(3*H) + j0);
            float4 bhz = *(const float4*)(g_whT + k*(3*H) + H + j0);
            float4 bhn = *(const float4*)(g_whT + k*(3*H) + 2*H + j0);
            const float* pir = &bir.x; const float* piz = &biz.x; const float* pin = &bin_.x;
            const float* phr = &bhr.x; const float* phz = &bhz.x; const float* phn = &bhn.x;
            float xi[4], xh[4];
            #pragma unroll
            for (int r = 0; r < 4; r++) {
                xi[r] = sX[(r0+r)*H + k];
                xh[r] = sA[(r0+r)*H + k];
            }
            #pragma unroll
            for (int r = 0; r < 4; r++)
                #pragma unroll
                for (int c = 0; c < 4; c++) {
                    aIr[r][c] = fmaf(xi[r], pir[c], aIr[r][c]);
                    aIz[r][c] = fmaf(xi[r], piz[c], aIz[r][c]);
                    aIn[r][c] = fmaf(xi[r], pin[c], aIn[r][c]);
                    aHr[r][c] = fmaf(xh[r], phr[c], aHr[r][c]);
                    aHz[r][c] = fmaf(xh[r], phz[c], aHz[r][c]);
                    aHn[r][c] = fmaf(xh[r], phn[c], aHn[r][c]);
                }
        }
        float4 bir4 = *(const float4*)(gbi + j0);
        float4 biz4 = *(const float4*)(gbi + H + j0);
        float4 bin4 = *(const float4*)(gbi + 2*H + j0);
        float4 bhr4 = *(const float4*)(gbh + j0);
        float4 bhz4 = *(const float4*)(gbh + H + j0);
        float4 bhn4 = *(const float4*)(gbh + 2*H + j0);
        const float* qir = &bir4.x; const float* qiz = &biz4.x; const float* qin = &bin4.x;
        const float* qhr = &bhr4.x; const float* qhz = &bhz4.x; const float* qhn = &bhn4.x;
        #pragma unroll
        for (int r = 0; r < 4; r++) {
            int row = row0 + r0 + r;
            #pragma unroll
            for (int c = 0; c < 4; c++) {
                float ir = aIr[r][c] + qir[c];
                float iz = aIz[r][c] + qiz[c];
                float in_ = aIn[r][c] + qin[c];
                float hr = aHr[r][c] + qhr[c];
                float hz = aHz[r][c] + qhz[c];
                float hn = aHn[r][c] + qhn[c];
                float rr = 1.f / (1.f + expf(-(ir + hr)));
                float zz = 1.f / (1.f + expf(-(iz + hz)));
                float nn = tanhf(in_ + rr * hn);
                float hp = sA[(r0+r)*H + j0 + c];
                float hv = (1.f - zz) * nn + zz * hp;
                g_h[row*H + j0 + c] = hv;
                out[OFF_H + row*H + j0 + c] = hv;
            }
        }
    }
}

// ---------------------------------------------------------------------------
// quantile embedding: q_phi[r] = relu(cos(pi*f*rq[r]) @ phi_w + b); also emit rq
__global__ void k_qphi(const float* __restrict__ rq,
                       const float* __restrict__ phi_w,
                       const float* __restrict__ phi_b,
                       float* __restrict__ out) {
    __shared__ float c[QED];
    int r = blockIdx.x;            // 0..4095
    int t = threadIdx.x;           // 128
    float rqv = rq[r];
    if (t < QED) c[t] = cospif((float)t * rqv);
    if (t == 0) out[OFF_RQ + r] = rqv;
    __syncthreads();
    float acc = phi_b[t];
    #pragma unroll 8
    for (int f = 0; f < QED; f++) acc = fmaf(c[f], phi_w[f*H + t], acc);
    g_qphi[r*H + t] = fmaxf(acc, 0.f);
}

// ---------------------------------------------------------------------------
// fc2 + transpose + sort along quantiles; one block per sample b
__global__ void k_fc2sort(const float* __restrict__ fc2_w,
                          const float* __restrict__ fc2_b,
                          float* __restrict__ out) {
    __shared__ float hq[H*NQ];      // [j][qi] layout -> conflict-free dot reads
    __shared__ float sq[NA*NQ];
    int b = blockIdx.x;
    int g = b >> 3;                 // b / NAG
    int t = threadIdx.x;            // 128
    for (int i = t; i < H*NQ; i += 128) {
        int qi = i >> 7, j = i & 127;
        hq[j*NQ + qi] = g_h[b*H + j] * g_qphi[(g*NQ + qi)*H + j];
    }
    __syncthreads();
    if (t < NA*NQ) {
        int na = t >> 3, qi = t & 7;
        float acc = fc2_b[na];
        #pragma unroll 8
        for (int j = 0; j < H; j++)
            acc = fmaf(hq[j*NQ + qi], fc2_w[j*NA + na], acc);
        sq[na*NQ + qi] = acc;
    }
    __syncthreads();
    if (t < NA) {
        float v[NQ];
        #pragma unroll
        for (int k = 0; k < NQ; k++) v[k] = sq[t*NQ + k];
        #pragma unroll
        for (int i = 1; i < NQ; i++) {      // insertion sort ascending
            float key = v[i];
            int p = i - 1;
            while (p >= 0 && v[p] > key) { v[p+1] = v[p]; p--; }
            v[p+1] = key;
        }
        #pragma unroll
        for (int k = 0; k < NQ; k++)
            out[OFF_SQ + b*(NA*NQ) + t*NQ + k] = v[k];
    }
}

// ---------------------------------------------------------------------------
extern "C" void kernel_launch(void* const* d_in, const int* in_sizes, int n_in,
                              void* d_out, int out_size) {
    const float* in        = (const float*)d_in[0];
    const float* hidden    = (const float*)d_in[1];
    const float* rqs       = (const float*)d_in[2];
    const float* fc1_w     = (const float*)d_in[3];
    const float* fc1_b     = (const float*)d_in[4];
    const float* hyp_w1    = (const float*)d_in[5];
    const float* hyp_b1    = (const float*)d_in[6];
    const float* hyp_w2    = (const float*)d_in[7];
    const float* hyp_b2    = (const float*)d_in[8];
    const float* merger_w  = (const float*)d_in[9];
    const float* gru_wi    = (const float*)d_in[10];
    const float* gru_wh    = (const float*)d_in[11];
    const float* gru_bi    = (const float*)d_in[12];
    const float* gru_bh    = (const float*)d_in[13];
    const float* phi_w     = (const float*)d_in[14];
    const float* phi_b     = (const float*)d_in[15];
    const float* fc2_w     = (const float*)d_in[16];
    const float* fc2_b     = (const float*)d_in[17];
    float* out = (float*)d_out;

    k_prep<<<1, 128>>>(hyp_w1, hyp_b1, merger_w);
    k_buildW<<<WSZ/256, 256>>>(hyp_w2, hyp_b2);
    k_transpose<<<(3*H*H)/256, 256>>>(gru_wi, gru_wh);
    k_main<<<BS/32, 256>>>(in, hidden, fc1_w, fc1_b, gru_bi, gru_bh, out);
    k_qphi<<<BSG*NQ, 128>>>(rqs, phi_w, phi_b, out);
    k_fc2sort<<<BS, 128>>>(fc2_w, fc2_b, out);
}

// round 3
// speedup vs baseline: 1.1357x; 1.1357x over previous
#include <cuda_runtime.h>
#include <math.h>

// dims
#define E    256
#define H    128
#define NQ   8
#define QED  64
#define HYP  64
#define NA   14
#define NAG  8
#define BS   4096
#define BSG  512
#define WSZ  32768

// output layout: sorted_q [BS,NA,NQ] | h [BS,H] | rq [BSG,NQ]
#define OFF_SQ 0
#define OFF_H  (BS*NA*NQ)
#define OFF_RQ (OFF_H + BS*H)

// scratch
__device__ __align__(16) float g_hh[HYP];
__device__ __align__(16) float g_msm[2*H];
__device__ __align__(16) float g_W[H*2*H];        // [128][256]
__device__ __align__(16) float g_wrz[2*H*2*H];    // [256][256]: k in [x2;h], j: r(0..127), z(128..255)
__device__ __align__(16) float g_wn[H*2*H];       // [128][256]: j: inn(0..127), hn(128..255)
__device__ __align__(16) float g_h[BS*H];
__device__ __align__(16) float g_qphi[BSG*NQ*H];

// f32x2 helpers
typedef unsigned long long u64t;
__device__ __forceinline__ u64t pk2(float a) {
    u64t r; asm("mov.b64 %0, {%1,%1};" : "=l"(r) : "f"(a)); return r;
}
__device__ __forceinline__ u64t pk2b(float a, float b) {
    u64t r; asm("mov.b64 %0, {%1,%2};" : "=l"(r) : "f"(a), "f"(b)); return r;
}
__device__ __forceinline__ void fma2(u64t& d, u64t a, u64t b) {
    asm("fma.rn.f32x2 %0, %1, %2, %3;" : "=l"(d) : "l"(a), "l"(b), "l"(d));
}
__device__ __forceinline__ float2 upk(u64t v) {
    float2 f; asm("mov.b64 {%0,%1}, %2;" : "=f"(f.x), "=f"(f.y) : "l"(v)); return f;
}
__device__ __forceinline__ float sigm(float x) {
    return __fdividef(1.f, 1.f + __expf(-x));
}

// ---------------------------------------------------------------------------
__global__ void k_prep(const float* __restrict__ hyp_w1,
                       const float* __restrict__ hyp_b1,
                       const float* __restrict__ merger_w) {
    int t = threadIdx.x;
    if (t < HYP) {
        float s = hyp_b1[t];
        #pragma unroll
        for (int q = 0; q < NQ; q++) s += hyp_w1[q*HYP + t];
        g_hh[t] = fmaxf(s, 0.f);
    }
    if (t < H) {
        float a = merger_w[t], b = merger_w[H + t];
        float m = fmaxf(a, b);
        float e0 = expf(a - m), e1 = expf(b - m);
        float inv = 1.f / (e0 + e1);
        g_msm[t]     = e0 * inv;
        g_msm[H + t] = e1 * inv;
    }
}

// ---------------------------------------------------------------------------
__global__ void k_buildW(const float* __restrict__ hyp_w2,
                         const float* __restrict__ hyp_b2) {
    __shared__ float sh[HYP];
    int t = threadIdx.x;
    if (t < HYP) sh[t] = g_hh[t];
    __syncthreads();
    int m = blockIdx.x * blockDim.x + t;
    float acc = hyp_b2[m];
    #pragma unroll 8
    for (int f = 0; f < HYP; f++) acc = fmaf(sh[f], hyp_w2[f*WSZ + m], acc);
    g_W[m] = acc;
}

// ---------------------------------------------------------------------------
// build combined GRU weights:
// g_wrz[k*256+j] : k<128 -> gru_wi[j*128+k] ; k>=128 -> gru_wh[j*128+(k-128)]
//   (j in 0..255 covers gates r (wi/wh rows 0..127) and z (rows 128..255))
// g_wn[k*256+j]  : j<128 -> gru_wi[(256+j)*128+k] (inn)
//                  j>=128 -> gru_wh[(128+j)*128+k] (hn)   [since 256+(j-128)=128+j]
__global__ void k_buildGRU(const float* __restrict__ gwi,
                           const float* __restrict__ gwh) {
    int idx = blockIdx.x * blockDim.x + threadIdx.x;   // 0..98303
    if (idx < 65536) {
        int k = idx >> 8, j = idx & 255;
        g_wrz[idx] = (k < 128) ? gwi[j*128 + k] : gwh[j*128 + (k - 128)];
    } else {
        int t = idx - 65536;
        int k = t >> 8, j = t & 255;
        g_wn[t] = (j < 128) ? gwi[(256 + j)*128 + k] : gwh[(128 + j)*128 + k];
    }
}

// ---------------------------------------------------------------------------
// fused main: fc1 -> emb -> merge -> GRU.  512 thr, 32 rows/block, 128 blocks.
// warp (tid>>5) -> 8 output cols; lane -> row.
// smem: sC [32][257] (input, later x2|h concat), sX [32][129] (x), sB [16384] weight tile
#define SC_STR 257
#define SX_STR 129
#define SC_FLOATS (32*SC_STR)
#define SX_FLOATS (32*SX_STR)
#define SB_FLOATS 16384
#define SMEM_BYTES ((SC_FLOATS + SX_FLOATS + SB_FLOATS)*4)

__global__ __launch_bounds__(512, 1)
void k_main(const float* __restrict__ in, const float* __restrict__ hprev,
            const float* __restrict__ fc1_w, const float* __restrict__ fc1_b,
            const float* __restrict__ gbi,  const float* __restrict__ gbh,
            float* __restrict__ out) {
    extern __shared__ float smem[];
    float* sC = smem;
    float* sX = smem + SC_FLOATS;
    float* sB = smem + SC_FLOATS + SX_FLOATS;
    float4* sB4 = (float4*)sB;

    const int tid  = threadIdx.x;
    const int lane = tid & 31;
    const int warp = tid >> 5;          // 0..15
    const int col0 = warp * 8;          // 0..120
    const int row0 = blockIdx.x * 32;

    // stage input A [32][256] -> sC (coalesced read, scalar scatter store)
    {
        const float4* src = (const float4*)(in + row0*E);
        for (int i = tid; i < 2048; i += 512) {
            float4 v = src[i];
            int f = i * 4;
            int r = f >> 8, c = f & 255;
            float* p = sC + r*SC_STR + c;
            p[0] = v.x; p[1] = v.y; p[2] = v.z; p[3] = v.w;
        }
    }

    // ---- fc1: x = relu(A @ fc1_w + b), KT=128, 2 tiles ----
    u64t X[4];
    {
        float4 bb0 = *(const float4*)(fc1_b + col0);
        float4 bb1 = *(const float4*)(fc1_b + col0 + 4);
        X[0] = pk2b(bb0.x, bb0.y); X[1] = pk2b(bb0.z, bb0.w);
        X[2] = pk2b(bb1.x, bb1.y); X[3] = pk2b(bb1.z, bb1.w);
        for (int kt = 0; kt < 256; kt += 128) {
            const float4* wsrc = (const float4*)(fc1_w + kt*H);
            for (int i = tid; i < 4096; i += 512) sB4[i] = wsrc[i];
            __syncthreads();
            const float* aP = sC + lane*SC_STR + kt;
            #pragma unroll 4
            for (int k = 0; k < 128; k++) {
                ulonglong2 b01 = *(const ulonglong2*)&sB[k*128 + col0];
                ulonglong2 b23 = *(const ulonglong2*)&sB[k*128 + col0 + 4];
                u64t pa = pk2(aP[k]);
                fma2(X[0], pa, b01.x); fma2(X[1], pa, b01.y);
                fma2(X[2], pa, b23.x); fma2(X[3], pa, b23.y);
            }
            __syncthreads();
        }
        // relu, write x to sX
        float* xo = sX + lane*SX_STR + col0;
        #pragma unroll
        for (int cc = 0; cc < 4; cc++) {
            float2 v = upk(X[cc]);
            xo[2*cc]   = fmaxf(v.x, 0.f);
            xo[2*cc+1] = fmaxf(v.y, 0.f);
        }
    }

    // ---- emb: e = x @ g_W[128][256], KT=64, 2 tiles ----
    u64t E0[4] = {0,0,0,0}, E1[4] = {0,0,0,0};
    for (int kt = 0; kt < 128; kt += 64) {
        const float4* wsrc = (const float4*)(g_W + kt*256);
        for (int i = tid; i < 4096; i += 512) sB4[i] = wsrc[i];
        __syncthreads();
        const float* aP = sX + lane*SX_STR + kt;
        #pragma unroll 2
        for (int k = 0; k < 64; k++) {
            ulonglong2 p01 = *(const ulonglong2*)&sB[k*256 + col0];
            ulonglong2 p23 = *(const ulonglong2*)&sB[k*256 + col0 + 4];
            ulonglong2 q01 = *(const ulonglong2*)&sB[k*256 + 128 + col0];
            ulonglong2 q23 = *(const ulonglong2*)&sB[k*256 + 128 + col0 + 4];
            u64t pa = pk2(aP[k]);
            fma2(E0[0], pa, p01.x); fma2(E0[1], pa, p01.y);
            fma2(E0[2], pa, p23.x); fma2(E0[3], pa, p23.y);
            fma2(E1[0], pa, q01.x); fma2(E1[1], pa, q01.y);
            fma2(E1[2], pa, q23.x); fma2(E1[3], pa, q23.y);
        }
        __syncthreads();
    }

    // ---- merge + relu -> x2 into sC[.., 0..128); stage hprev into sC[.., 128..256) ----
    {
        float4 m0a = *(const float4*)(g_msm + col0);
        float4 m0b = *(const float4*)(g_msm + col0 + 4);
        float4 m1a = *(const float4*)(g_msm + H + col0);
        float4 m1b = *(const float4*)(g_msm + H + col0 + 4);
        const float* m0 = &m0a.x;   // m0a,m0b contiguous on stack? avoid: handle explicitly
        (void)m0;
        float m0v[8] = {m0a.x,m0a.y,m0a.z,m0a.w,m0b.x,m0b.y,m0b.z,m0b.w};
        float m1v[8] = {m1a.x,m1a.y,m1a.z,m1a.w,m1b.x,m1b.y,m1b.z,m1b.w};
        float* xo = sC + lane*SC_STR + col0;
        #pragma unroll
        for (int cc = 0; cc < 4; cc++) {
            float2 a = upk(E0[cc]);
            float2 b = upk(E1[cc]);
            xo[2*cc]   = fmaxf(fmaf(m0v[2*cc],   a.x, m1v[2*cc]  *b.x), 0.f);
            xo[2*cc+1] = fmaxf(fmaf(m0v[2*cc+1], a.y, m1v[2*cc+1]*b.y), 0.f);
        }
        const float4* hsrc = (const float4*)(hprev + row0*H);
        for (int i = tid; i < 1024; i += 512) {
            float4 v = hsrc[i];
            int f = i * 4;
            int r = f >> 7, c = f & 127;
            float* p = sC + r*SC_STR + 128 + c;
            p[0] = v.x; p[1] = v.y; p[2] = v.z; p[3] = v.w;
        }
    }

    // ---- GRU r,z: concat [x2;h] @ g_wrz[256][256], KT=64, 4 tiles ----
    float r8[8], z8[8];
    {
        u64t Ar[4], Az[4];
        float4 bi0 = *(const float4*)(gbi + col0);
        float4 bi1 = *(const float4*)(gbi + col0 + 4);
        float4 bh0 = *(const float4*)(gbh + col0);
        float4 bh1 = *(const float4*)(gbh + col0 + 4);
        Ar[0] = pk2b(bi0.x + bh0.x, bi0.y + bh0.y);
        Ar[1] = pk2b(bi0.z + bh0.z, bi0.w + bh0.w);
        Ar[2] = pk2b(bi1.x + bh1.x, bi1.y + bh1.y);
        Ar[3] = pk2b(bi1.z + bh1.z, bi1.w + bh1.w);
        float4 ci0 = *(const float4*)(gbi + H + col0);
        float4 ci1 = *(const float4*)(gbi + H + col0 + 4);
        float4 ch0 = *(const float4*)(gbh + H + col0);
        float4 ch1 = *(const float4*)(gbh + H + col0 + 4);
        Az[0] = pk2b(ci0.x + ch0.x, ci0.y + ch0.y);
        Az[1] = pk2b(ci0.z + ch0.z, ci0.w + ch0.w);
        Az[2] = pk2b(ci1.x + ch1.x, ci1.y + ch1.y);
        Az[3] = pk2b(ci1.z + ch1.z, ci1.w + ch1.w);

        for (int kt = 0; kt < 256; kt += 64) {
            const float4* wsrc = (const float4*)(g_wrz + kt*256);
            for (int i = tid; i < 4096; i += 512) sB4[i] = wsrc[i];
            __syncthreads();
            const float* aP = sC + lane*SC_STR + kt;
            #pragma unroll 2
            for (int k = 0; k < 64; k++) {
                ulonglong2 p01 = *(const ulonglong2*)&sB[k*256 + col0];
                ulonglong2 p23 = *(const ulonglong2*)&sB[k*256 + col0 + 4];
                ulonglong2 q01 = *(const ulonglong2*)&sB[k*256 + 128 + col0];
                ulonglong2 q23 = *(const ulonglong2*)&sB[k*256 + 128 + col0 + 4];
                u64t pa = pk2(aP[k]);
                fma2(Ar[0], pa, p01.x); fma2(Ar[1], pa, p01.y);
                fma2(Ar[2], pa, p23.x); fma2(Ar[3], pa, p23.y);
                fma2(Az[0], pa, q01.x); fma2(Az[1], pa, q01.y);
                fma2(Az[2], pa, q23.x); fma2(Az[3], pa, q23.y);
            }
            __syncthreads();
        }
        #pragma unroll
        for (int cc = 0; cc < 4; cc++) {
            float2 rv = upk(Ar[cc]);
            float2 zv = upk(Az[cc]);
            r8[2*cc] = sigm(rv.x); r8[2*cc+1] = sigm(rv.y);
            z8[2*cc] = sigm(zv.x); z8[2*cc+1] = sigm(zv.y);
        }
    }

    // ---- GRU n: inn/hn over g_wn[128][256], KT=64, 2 tiles ----
    {
        u64t An[4], Ah[4];
        float4 ni0 = *(const float4*)(gbi + 2*H + col0);
        float4 ni1 = *(const float4*)(gbi + 2*H + col0 + 4);
        float4 nh0 = *(const float4*)(gbh + 2*H + col0);
        float4 nh1 = *(const float4*)(gbh + 2*H + col0 + 4);
        An[0] = pk2b(ni0.x, ni0.y); An[1] = pk2b(ni0.z, ni0.w);
        An[2] = pk2b(ni1.x, ni1.y); An[3] = pk2b(ni1.z, ni1.w);
        Ah[0] = pk2b(nh0.x, nh0.y); Ah[1] = pk2b(nh0.z, nh0.w);
        Ah[2] = pk2b(nh1.x, nh1.y); Ah[3] = pk2b(nh1.z, nh1.w);

        for (int kt = 0; kt < 128; kt += 64) {
            const float4* wsrc = (const float4*)(g_wn + kt*256);
            for (int i = tid; i < 4096; i += 512) sB4[i] = wsrc[i];
            __syncthreads();
            const float* aP = sC + lane*SC_STR + kt;
            #pragma unroll 2
            for (int k = 0; k < 64; k++) {
                ulonglong2 p01 = *(const ulonglong2*)&sB[k*256 + col0];
                ulonglong2 p23 = *(const ulonglong2*)&sB[k*256 + col0 + 4];
                ulonglong2 q01 = *(const ulonglong2*)&sB[k*256 + 128 + col0];
                ulonglong2 q23 = *(const ulonglong2*)&sB[k*256 + 128 + col0 + 4];
                u64t pi = pk2(aP[k]);          // x2[k]
                u64t ph = pk2(aP[k + 128]);    // h[k]
                fma2(An[0], pi, p01.x); fma2(An[1], pi, p01.y);
                fma2(An[2], pi, p23.x); fma2(An[3], pi, p23.y);
                fma2(Ah[0], ph, q01.x); fma2(Ah[1], ph, q01.y);
                fma2(Ah[2], ph, q23.x); fma2(Ah[3], ph, q23.y);
            }
            __syncthreads();
        }

        // finalize h
        float hv[8];
        const float* hpP = sC + lane*SC_STR + 128 + col0;
        #pragma unroll
        for (int cc = 0; cc < 4; cc++) {
            float2 nv = upk(An[cc]);
            float2 hnv = upk(Ah[cc]);
            float n0 = tanhf(fmaf(r8[2*cc],   hnv.x, nv.x));
            float n1 = tanhf(fmaf(r8[2*cc+1], hnv.y, nv.y));
            float hp0 = hpP[2*cc], hp1 = hpP[2*cc+1];
            hv[2*cc]   = (1.f - z8[2*cc])  * n0 + z8[2*cc]  * hp0;
            hv[2*cc+1] = (1.f - z8[2*cc+1])* n1 + z8[2*cc+1]* hp1;
        }
        int row = row0 + lane;
        float4 o0 = make_float4(hv[0], hv[1], hv[2], hv[3]);
        float4 o1 = make_float4(hv[4], hv[5], hv[6], hv[7]);
        *(float4*)&out[OFF_H + row*H + col0]     = o0;
        *(float4*)&out[OFF_H + row*H + col0 + 4] = o1;
        *(float4*)&g_h[row*H + col0]     = o0;
        *(float4*)&g_h[row*H + col0 + 4] = o1;
    }
}

// ---------------------------------------------------------------------------
__global__ void k_qphi(const float* __restrict__ rq,
                       const float* __restrict__ phi_w,
                       const float* __restrict__ phi_b,
                       float* __restrict__ out) {
    __shared__ float c[QED];
    int r = blockIdx.x;
    int t = threadIdx.x;
    float rqv = rq[r];
    if (t < QED) c[t] = cospif((float)t * rqv);
    if (t == 0) out[OFF_RQ + r] = rqv;
    __syncthreads();
    float acc = phi_b[t];
    #pragma unroll 8
    for (int f = 0; f < QED; f++) acc = fmaf(c[f], phi_w[f*H + t], acc);
    g_qphi[r*H + t] = fmaxf(acc, 0.f);
}

// ---------------------------------------------------------------------------
__global__ void k_fc2sort(const float* __restrict__ fc2_w,
                          const float* __restrict__ fc2_b,
                          float* __restrict__ out) {
    __shared__ float hq[H*NQ];
    __shared__ float sq[NA*NQ];
    int b = blockIdx.x;
    int g = b >> 3;
    int t = threadIdx.x;
    for (int i = t; i < H*NQ; i += 128) {
        int qi = i >> 7, j = i & 127;
        hq[j*NQ + qi] = g_h[b*H + j] * g_qphi[(g*NQ + qi)*H + j];
    }
    __syncthreads();
    if (t < NA*NQ) {
        int na = t >> 3, qi = t & 7;
        float acc = fc2_b[na];
        #pragma unroll 8
        for (int j = 0; j < H; j++)
            acc = fmaf(hq[j*NQ + qi], fc2_w[j*NA + na], acc);
        sq[na*NQ + qi] = acc;
    }
    __syncthreads();
    if (t < NA) {
        float v[NQ];
        #pragma unroll
        for (int k = 0; k < NQ; k++) v[k] = sq[t*NQ + k];
        #pragma unroll
        for (int i = 1; i < NQ; i++) {
            float key = v[i];
            int p = i - 1;
            while (p >= 0 && v[p] > key) { v[p+1] = v[p]; p--; }
            v[p+1] = key;
        }
        #pragma unroll
        for (int k = 0; k < NQ; k++)
            out[OFF_SQ + b*(NA*NQ) + t*NQ + k] = v[k];
    }
}

// ---------------------------------------------------------------------------
extern "C" void kernel_launch(void* const* d_in, const int* in_sizes, int n_in,
                              void* d_out, int out_size) {
    const float* in        = (const float*)d_in[0];
    const float* hidden    = (const float*)d_in[1];
    const float* rqs       = (const float*)d_in[2];
    const float* fc1_w     = (const float*)d_in[3];
    const float* fc1_b     = (const float*)d_in[4];
    const float* hyp_w1    = (const float*)d_in[5];
    const float* hyp_b1    = (const float*)d_in[6];
    const float* hyp_w2    = (const float*)d_in[7];
    const float* hyp_b2    = (const float*)d_in[8];
    const float* merger_w  = (const float*)d_in[9];
    const float* gru_wi    = (const float*)d_in[10];
    const float* gru_wh    = (const float*)d_in[11];
    const float* gru_bi    = (const float*)d_in[12];
    const float* gru_bh    = (const float*)d_in[13];
    const float* phi_w     = (const float*)d_in[14];
    const float* phi_b     = (const float*)d_in[15];
    const float* fc2_w     = (const float*)d_in[16];
    const float* fc2_b     = (const float*)d_in[17];
    float* out = (float*)d_out;

    static int smem_set = 0;
    if (!smem_set) {
        cudaFuncSetAttribute(k_main, cudaFuncAttributeMaxDynamicSharedMemorySize,
                             SMEM_BYTES);
        smem_set = 1;
    }

    k_prep<<<1, 128>>>(hyp_w1, hyp_b1, merger_w);
    k_buildW<<<WSZ/256, 256>>>(hyp_w2, hyp_b2);
    k_buildGRU<<<384, 256>>>(gru_wi, gru_wh);
    k_main<<<BS/32, 512, SMEM_BYTES>>>(in, hidden, fc1_w, fc1_b, gru_bi, gru_bh, out);
    k_qphi<<<BSG*NQ, 128>>>(rqs, phi_w, phi_b, out);
    k_fc2sort<<<BS, 128>>>(fc2_w, fc2_b, out);
}

// round 4
// speedup vs baseline: 1.4401x; 1.2680x over previous
#include <cuda_runtime.h>
#include <math.h>

// dims
#define E    256
#define H    128
#define NQ   8
#define QED  64
#define HYP  64
#define NA   14
#define NAG  8
#define BS   4096
#define BSG  512
#define WSZ  32768

// output layout: sorted_q [BS,NA,NQ] | h [BS,H] | rq [BSG,NQ]
#define OFF_SQ 0
#define OFF_H  (BS*NA*NQ)
#define OFF_RQ (OFF_H + BS*H)

// scratch
__device__ __align__(16) float g_msm[2*H];
__device__ __align__(16) float g_W[H*2*H];        // [128][256]
__device__ __align__(16) float g_wrz[2*H*2*H];    // [256][256]
__device__ __align__(16) float g_wn[H*2*H];       // [128][256]
__device__ __align__(16) float g_h[BS*H];
__device__ __align__(16) float g_qphi[BSG*NQ*H];

typedef unsigned long long u64t;
__device__ __forceinline__ u64t pk2(float a) {
    u64t r; asm("mov.b64 %0, {%1,%1};" : "=l"(r) : "f"(a)); return r;
}
__device__ __forceinline__ u64t pk2b(float a, float b) {
    u64t r; asm("mov.b64 %0, {%1,%2};" : "=l"(r) : "f"(a), "f"(b)); return r;
}
__device__ __forceinline__ void fma2(u64t& d, u64t a, u64t b) {
    asm("fma.rn.f32x2 %0, %1, %2, %3;" : "=l"(d) : "l"(a), "l"(b), "l"(d));
}
__device__ __forceinline__ float2 upk(u64t v) {
    float2 f; asm("mov.b64 {%0,%1}, %2;" : "=f"(f.x), "=f"(f.y) : "l"(v)); return f;
}
__device__ __forceinline__ float sigm(float x) {
    return __fdividef(1.f, 1.f + __expf(-x));
}

// cp.async helpers
__device__ __forceinline__ void cpa16(unsigned s, const void* g) {
    asm volatile("cp.async.cg.shared.global [%0], [%1], 16;" :: "r"(s), "l"(g));
}
__device__ __forceinline__ void cpcommit() { asm volatile("cp.async.commit_group;"); }
__device__ __forceinline__ void cpwait1()  { asm volatile("cp.async.wait_group 1;"); }
__device__ __forceinline__ void cpwait0()  { asm volatile("cp.async.wait_group 0;"); }

// ---------------------------------------------------------------------------
// merged weight-prep + qphi kernel. 128 threads/block.
// blocks [0,256): buildW ; [256,768): g_wrz ; [768,1024): g_wn ;
// 1024: msm ; [1025, 1025+4096): qphi
__global__ void k_wprep(const float* __restrict__ hyp_w1,
                        const float* __restrict__ hyp_b1,
                        const float* __restrict__ hyp_w2,
                        const float* __restrict__ hyp_b2,
                        const float* __restrict__ merger_w,
                        const float* __restrict__ gwi,
                        const float* __restrict__ gwh,
                        const float* __restrict__ rq,
                        const float* __restrict__ phi_w,
                        const float* __restrict__ phi_b,
                        float* __restrict__ out) {
    int bid = blockIdx.x, t = threadIdx.x;
    if (bid < 256) {
        __shared__ float sh[HYP];
        if (t < HYP) {
            float s = hyp_b1[t];
            #pragma unroll
            for (int q = 0; q < NQ; q++) s += hyp_w1[q*HYP + t];
            sh[t] = fmaxf(s, 0.f);
        }
        __syncthreads();
        int m = bid*128 + t;
        float acc = hyp_b2[m];
        #pragma unroll 8
        for (int f = 0; f < HYP; f++) acc = fmaf(sh[f], hyp_w2[f*WSZ + m], acc);
        g_W[m] = acc;
    } else if (bid < 768) {
        int idx = (bid - 256)*128 + t;     // 0..65535
        int k = idx >> 8, j = idx & 255;
        g_wrz[idx] = (k < 128) ? gwi[j*128 + k] : gwh[j*128 + (k - 128)];
    } else if (bid < 1024) {
        int idx = (bid - 768)*128 + t;     // 0..32767
        int k = idx >> 8, j = idx & 255;
        g_wn[idx] = (j < 128) ? gwi[(256 + j)*128 + k] : gwh[(128 + j)*128 + k];
    } else if (bid == 1024) {
        if (t < H) {
            float a = merger_w[t], b = merger_w[H + t];
            float m = fmaxf(a, b);
            float e0 = expf(a - m), e1 = expf(b - m);
            float inv = 1.f / (e0 + e1);
            g_msm[t]     = e0 * inv;
            g_msm[H + t] = e1 * inv;
        }
    } else {
        __shared__ float c[QED];
        int r = bid - 1025;                // 0..4095
        float rqv = rq[r];
        if (t < QED) c[t] = cospif((float)t * rqv);
        if (t == 0) out[OFF_RQ + r] = rqv;
        __syncthreads();
        float acc = phi_b[t];
        #pragma unroll 8
        for (int f = 0; f < QED; f++) acc = fmaf(c[f], phi_w[f*H + t], acc);
        g_qphi[r*H + t] = fmaxf(acc, 0.f);
    }
}

// ---------------------------------------------------------------------------
// fused main: fc1 -> emb -> merge -> GRU.
// 256 threads, 32 rows/block, 128 blocks.
// thread: warp w, lane l. rowA = l&15 (rows rowA, rowA+16); colhalf = l>>4;
// c0 = w*16 + colhalf*8  -> 8 output cols per thread, 2 rows.
// smem: sC [32][257] (input -> x2|h concat), sX [32][129] (x),
//       sB 3 x 4096 floats (16KB weight tiles, cp.async triple-buffered)
#define SC_STR 257
#define SX_STR 129
#define SC_F (32*SC_STR)
#define SX_F (32*SX_STR)
#define SB_F (3*4096)
#define SMEM_BYTES ((SC_F + SX_F + SB_F)*4)

__device__ __forceinline__ void stage16k(unsigned sbu, int bufi,
                                         const float* src, int tid) {
    unsigned d = sbu + (unsigned)(bufi*16384 + tid*16);
    const char* s = (const char*)src + tid*16;
    #pragma unroll
    for (int i = 0; i < 4; i++) cpa16(d + i*4096, s + i*4096);
}

__global__ __launch_bounds__(256, 1)
void k_main(const float* __restrict__ in, const float* __restrict__ hprev,
            const float* __restrict__ fc1_w, const float* __restrict__ fc1_b,
            const float* __restrict__ gbi,  const float* __restrict__ gbh,
            float* __restrict__ out) {
    extern __shared__ float smem[];
    float* sC = smem;
    float* sX = smem + SC_F;
    float* sB = smem + SC_F + SX_F;
    unsigned sbu = (unsigned)__cvta_generic_to_shared(sB);

    const int tid  = threadIdx.x;
    const int lane = tid & 31;
    const int warp = tid >> 5;              // 0..7
    const int rowA = lane & 15;
    const int c0   = warp*16 + (lane >> 4)*8;
    const int row0 = blockIdx.x * 32;

    // stage input A [32][256] -> sC
    {
        const float4* src = (const float4*)(in + row0*E);
        #pragma unroll
        for (int i = tid; i < 2048; i += 256) {
            float4 v = src[i];
            int f = i * 4;
            int r = f >> 8, cc = f & 255;
            float* p = sC + r*SC_STR + cc;
            p[0] = v.x; p[1] = v.y; p[2] = v.z; p[3] = v.w;
        }
    }
    // prologue: stage global tile 0 (fc1 tile 0)
    stage16k(sbu, 0, fc1_w, tid); cpcommit();

    // ======== FC1 : tiles g=0..7, KT=32, width 128 ========
    u64t X0[4], X1[4];
    {
        float4 b0 = *(const float4*)(fc1_b + c0);
        float4 b1 = *(const float4*)(fc1_b + c0 + 4);
        X0[0] = pk2b(b0.x, b0.y); X0[1] = pk2b(b0.z, b0.w);
        X0[2] = pk2b(b1.x, b1.y); X0[3] = pk2b(b1.z, b1.w);
        X1[0] = X0[0]; X1[1] = X0[1]; X1[2] = X0[2]; X1[3] = X0[3];
    }
    #pragma unroll 1
    for (int t = 0; t < 8; t++) {
        int g = t;
        const float* nsrc = (t < 7) ? (fc1_w + (t+1)*4096) : g_W;
        stage16k(sbu, (g+1)%3, nsrc, tid); cpcommit();
        cpwait1();
        __syncthreads();
        const float* bw  = sB + (g%3)*4096;
        const float* a0p = sC + rowA*SC_STR + t*32;
        const float* a1p = a0p + 16*SC_STR;
        #pragma unroll 8
        for (int kk = 0; kk < 32; kk++) {
            const float* wr = bw + kk*128 + c0;
            ulonglong2 w01 = *(const ulonglong2*)wr;
            ulonglong2 w23 = *(const ulonglong2*)(wr + 4);
            u64t a0 = pk2(a0p[kk]);
            u64t a1 = pk2(a1p[kk]);
            fma2(X0[0], a0, w01.x); fma2(X0[1], a0, w01.y);
            fma2(X0[2], a0, w23.x); fma2(X0[3], a0, w23.y);
            fma2(X1[0], a1, w01.x); fma2(X1[1], a1, w01.y);
            fma2(X1[2], a1, w23.x); fma2(X1[3], a1, w23.y);
        }
    }
    // relu, write x to sX
    {
        float* xo0 = sX + rowA*SX_STR + c0;
        float* xo1 = xo0 + 16*SX_STR;
        #pragma unroll
        for (int cc = 0; cc < 4; cc++) {
            float2 v0 = upk(X0[cc]);
            float2 v1 = upk(X1[cc]);
            xo0[2*cc]   = fmaxf(v0.x, 0.f); xo0[2*cc+1] = fmaxf(v0.y, 0.f);
            xo1[2*cc]   = fmaxf(v1.x, 0.f); xo1[2*cc+1] = fmaxf(v1.y, 0.f);
        }
    }

    // ======== EMB : tiles g=8..15, KT=16, width 256 ========
    u64t P0[4] = {0,0,0,0}, P1[4] = {0,0,0,0};   // head0 rows 0/1
    u64t Q0[4] = {0,0,0,0}, Q1[4] = {0,0,0,0};   // head1
    #pragma unroll 1
    for (int t = 0; t < 8; t++) {
        int g = 8 + t;
        const float* nsrc = (t < 7) ? (g_W + (t+1)*4096) : g_wrz;
        stage16k(sbu, (g+1)%3, nsrc, tid); cpcommit();
        cpwait1();
        __syncthreads();
        const float* bw  = sB + (g%3)*4096;
        const float* a0p = sX + rowA*SX_STR + t*16;
        const float* a1p = a0p + 16*SX_STR;
        #pragma unroll 4
        for (int kk = 0; kk < 16; kk++) {
            const float* wr0 = bw + kk*256 + c0;
            ulonglong2 p01 = *(const ulonglong2*)wr0;
            ulonglong2 p23 = *(const ulonglong2*)(wr0 + 4);
            ulonglong2 q01 = *(const ulonglong2*)(wr0 + 128);
            ulonglong2 q23 = *(const ulonglong2*)(wr0 + 132);
            u64t a0 = pk2(a0p[kk]);
            u64t a1 = pk2(a1p[kk]);
            fma2(P0[0], a0, p01.x); fma2(P0[1], a0, p01.y);
            fma2(P0[2], a0, p23.x); fma2(P0[3], a0, p23.y);
            fma2(P1[0], a1, p01.x); fma2(P1[1], a1, p01.y);
            fma2(P1[2], a1, p23.x); fma2(P1[3], a1, p23.y);
            fma2(Q0[0], a0, q01.x); fma2(Q0[1], a0, q01.y);
            fma2(Q0[2], a0, q23.x); fma2(Q0[3], a0, q23.y);
            fma2(Q1[0], a1, q01.x); fma2(Q1[1], a1, q01.y);
            fma2(Q1[2], a1, q23.x); fma2(Q1[3], a1, q23.y);
        }
    }

    // ---- merge + relu -> x2 into sC cols [0,128); stage hprev -> sC cols [128,256)
    {
        float4 m0a = *(const float4*)(g_msm + c0);
        float4 m0b = *(const float4*)(g_msm + c0 + 4);
        float4 m1a = *(const float4*)(g_msm + H + c0);
        float4 m1b = *(const float4*)(g_msm + H + c0 + 4);
        float m0v[8] = {m0a.x,m0a.y,m0a.z,m0a.w,m0b.x,m0b.y,m0b.z,m0b.w};
        float m1v[8] = {m1a.x,m1a.y,m1a.z,m1a.w,m1b.x,m1b.y,m1b.z,m1b.w};
        float* co0 = sC + rowA*SC_STR + c0;
        float* co1 = co0 + 16*SC_STR;
        #pragma unroll
        for (int cc = 0; cc < 4; cc++) {
            float2 a0 = upk(P0[cc]); float2 b0 = upk(Q0[cc]);
            float2 a1 = upk(P1[cc]); float2 b1 = upk(Q1[cc]);
            co0[2*cc]   = fmaxf(fmaf(m0v[2*cc],   a0.x, m1v[2*cc]  *b0.x), 0.f);
            co0[2*cc+1] = fmaxf(fmaf(m0v[2*cc+1], a0.y, m1v[2*cc+1]*b0.y), 0.f);
            co1[2*cc]   = fmaxf(fmaf(m0v[2*cc],   a1.x, m1v[2*cc]  *b1.x), 0.f);
            co1[2*cc+1] = fmaxf(fmaf(m0v[2*cc+1], a1.y, m1v[2*cc+1]*b1.y), 0.f);
        }
        const float4* hsrc = (const float4*)(hprev + row0*H);
        #pragma unroll
        for (int i = tid; i < 1024; i += 256) {
            float4 v = hsrc[i];
            int f = i * 4;
            int r = f >> 7, cc = f & 127;
            float* p = sC + r*SC_STR + 128 + cc;
            p[0] = v.x; p[1] = v.y; p[2] = v.z; p[3] = v.w;
        }
    }

    // ======== GRU r,z : tiles g=16..31, KT=16, width 256 ========
    float rs[2][8], zs[2][8];
    {
        u64t R0[4], R1[4], Z0[4], Z1[4];
        {
            float4 bi0 = *(const float4*)(gbi + c0);
            float4 bi1 = *(const float4*)(gbi + c0 + 4);
            float4 bh0 = *(const float4*)(gbh + c0);
            float4 bh1 = *(const float4*)(gbh + c0 + 4);
            R0[0] = pk2b(bi0.x+bh0.x, bi0.y+bh0.y);
            R0[1] = pk2b(bi0.z+bh0.z, bi0.w+bh0.w);
            R0[2] = pk2b(bi1.x+bh1.x, bi1.y+bh1.y);
            R0[3] = pk2b(bi1.z+bh1.z, bi1.w+bh1.w);
            float4 ci0 = *(const float4*)(gbi + H + c0);
            float4 ci1 = *(const float4*)(gbi + H + c0 + 4);
            float4 ch0 = *(const float4*)(gbh + H + c0);
            float4 ch1 = *(const float4*)(gbh + H + c0 + 4);
            Z0[0] = pk2b(ci0.x+ch0.x, ci0.y+ch0.y);
            Z0[1] = pk2b(ci0.z+ch0.z, ci0.w+ch0.w);
            Z0[2] = pk2b(ci1.x+ch1.x, ci1.y+ch1.y);
            Z0[3] = pk2b(ci1.z+ch1.z, ci1.w+ch1.w);
            #pragma unroll
            for (int i = 0; i < 4; i++) { R1[i] = R0[i]; Z1[i] = Z0[i]; }
        }
        #pragma unroll 1
        for (int t = 0; t < 16; t++) {
            int g = 16 + t;
            const float* nsrc = (t < 15) ? (g_wrz + (t+1)*4096) : g_wn;
            stage16k(sbu, (g+1)%3, nsrc, tid); cpcommit();
            cpwait1();
            __syncthreads();
            const float* bw  = sB + (g%3)*4096;
            const float* a0p = sC + rowA*SC_STR + t*16;
            const float* a1p = a0p + 16*SC_STR;
            #pragma unroll 4
            for (int kk = 0; kk < 16; kk++) {
                const float* wr0 = bw + kk*256 + c0;
                ulonglong2 p01 = *(const ulonglong2*)wr0;
                ulonglong2 p23 = *(const ulonglong2*)(wr0 + 4);
                ulonglong2 q01 = *(const ulonglong2*)(wr0 + 128);
                ulonglong2 q23 = *(const ulonglong2*)(wr0 + 132);
                u64t a0 = pk2(a0p[kk]);
                u64t a1 = pk2(a1p[kk]);
                fma2(R0[0], a0, p01.x); fma2(R0[1], a0, p01.y);
                fma2(R0[2], a0, p23.x); fma2(R0[3], a0, p23.y);
                fma2(R1[0], a1, p01.x); fma2(R1[1], a1, p01.y);
                fma2(R1[2], a1, p23.x); fma2(R1[3], a1, p23.y);
                fma2(Z0[0], a0, q01.x); fma2(Z0[1], a0, q01.y);
                fma2(Z0[2], a0, q23.x); fma2(Z0[3], a0, q23.y);
                fma2(Z1[0], a1, q01.x); fma2(Z1[1], a1, q01.y);
                fma2(Z1[2], a1, q23.x); fma2(Z1[3], a1, q23.y);
            }
        }
        #pragma unroll
        for (int cc = 0; cc < 4; cc++) {
            float2 r0 = upk(R0[cc]); float2 r1 = upk(R1[cc]);
            float2 z0 = upk(Z0[cc]); float2 z1 = upk(Z1[cc]);
            rs[0][2*cc] = sigm(r0.x); rs[0][2*cc+1] = sigm(r0.y);
            rs[1][2*cc] = sigm(r1.x); rs[1][2*cc+1] = sigm(r1.y);
            zs[0][2*cc] = sigm(z0.x); zs[0][2*cc+1] = sigm(z0.y);
            zs[1][2*cc] = sigm(z1.x); zs[1][2*cc+1] = sigm(z1.y);
        }
    }

    // ======== GRU n : tiles g=32..39, KT=16, width 256 ========
    {
        u64t N0[4], N1[4], G0[4], G1[4];
        {
            float4 ni0 = *(const float4*)(gbi + 2*H + c0);
            float4 ni1 = *(const float4*)(gbi + 2*H + c0 + 4);
            float4 nh0 = *(const float4*)(gbh + 2*H + c0);
            float4 nh1 = *(const float4*)(gbh + 2*H + c0 + 4);
            N0[0] = pk2b(ni0.x, ni0.y); N0[1] = pk2b(ni0.z, ni0.w);
            N0[2] = pk2b(ni1.x, ni1.y); N0[3] = pk2b(ni1.z, ni1.w);
            G0[0] = pk2b(nh0.x, nh0.y); G0[1] = pk2b(nh0.z, nh0.w);
            G0[2] = pk2b(nh1.x, nh1.y); G0[3] = pk2b(nh1.z, nh1.w);
            #pragma unroll
            for (int i = 0; i < 4; i++) { N1[i] = N0[i]; G1[i] = G0[i]; }
        }
        #pragma unroll 1
        for (int t = 0; t < 8; t++) {
            int g = 32 + t;
            if (t < 7) { stage16k(sbu, (g+1)%3, g_wn + (t+1)*4096, tid); cpcommit(); cpwait1(); }
            else cpwait0();
            __syncthreads();
            const float* bw  = sB + (g%3)*4096;
            const float* a0p = sC + rowA*SC_STR + t*16;
            const float* a1p = a0p + 16*SC_STR;
            #pragma unroll 4
            for (int kk = 0; kk < 16; kk++) {
                const float* wr0 = bw + kk*256 + c0;
                ulonglong2 p01 = *(const ulonglong2*)wr0;
                ulonglong2 p23 = *(const ulonglong2*)(wr0 + 4);
                ulonglong2 q01 = *(const ulonglong2*)(wr0 + 128);
                ulonglong2 q23 = *(const ulonglong2*)(wr0 + 132);
                u64t x0 = pk2(a0p[kk]);
                u64t x1 = pk2(a1p[kk]);
                u64t h0 = pk2(a0p[kk + 128]);
                u64t h1 = pk2(a1p[kk + 128]);
                fma2(N0[0], x0, p01.x); fma2(N0[1], x0, p01.y);
                fma2(N0[2], x0, p23.x); fma2(N0[3], x0, p23.y);
                fma2(N1[0], x1, p01.x); fma2(N1[1], x1, p01.y);
                fma2(N1[2], x1, p23.x); fma2(N1[3], x1, p23.y);
                fma2(G0[0], h0, q01.x); fma2(G0[1], h0, q01.y);
                fma2(G0[2], h0, q23.x); fma2(G0[3], h0, q23.y);
                fma2(G1[0], h1, q01.x); fma2(G1[1], h1, q01.y);
                fma2(G1[2], h1, q23.x); fma2(G1[3], h1, q23.y);
            }
        }

        // finalize h for 2 rows x 8 cols
        float hv0[8], hv1[8];
        const float* hp0 = sC + rowA*SC_STR + 128 + c0;
        const float* hp1 = hp0 + 16*SC_STR;
        #pragma unroll
        for (int cc = 0; cc < 4; cc++) {
            float2 nv0 = upk(N0[cc]); float2 gv0 = upk(G0[cc]);
            float2 nv1 = upk(N1[cc]); float2 gv1 = upk(G1[cc]);
            float n00 = tanhf(fmaf(rs[0][2*cc],   gv0.x, nv0.x));
            float n01 = tanhf(fmaf(rs[0][2*cc+1], gv0.y, nv0.y));
            float n10 = tanhf(fmaf(rs[1][2*cc],   gv1.x, nv1.x));
            float n11 = tanhf(fmaf(rs[1][2*cc+1], gv1.y, nv1.y));
            hv0[2*cc]   = (1.f - zs[0][2*cc])  * n00 + zs[0][2*cc]  * hp0[2*cc];
            hv0[2*cc+1] = (1.f - zs[0][2*cc+1])* n01 + zs[0][2*cc+1]* hp0[2*cc+1];
            hv1[2*cc]   = (1.f - zs[1][2*cc])  * n10 + zs[1][2*cc]  * hp1[2*cc];
            hv1[2*cc+1] = (1.f - zs[1][2*cc+1])* n11 + zs[1][2*cc+1]* hp1[2*cc+1];
        }
        int r0g = row0 + rowA, r1g = r0g + 16;
        float4 oa = make_float4(hv0[0], hv0[1], hv0[2], hv0[3]);
        float4 ob = make_float4(hv0[4], hv0[5], hv0[6], hv0[7]);
        float4 oc = make_float4(hv1[0], hv1[1], hv1[2], hv1[3]);
        float4 od = make_float4(hv1[4], hv1[5], hv1[6], hv1[7]);
        *(float4*)&out[OFF_H + r0g*H + c0]     = oa;
        *(float4*)&out[OFF_H + r0g*H + c0 + 4] = ob;
        *(float4*)&out[OFF_H + r1g*H + c0]     = oc;
        *(float4*)&out[OFF_H + r1g*H + c0 + 4] = od;
        *(float4*)&g_h[r0g*H + c0]     = oa;
        *(float4*)&g_h[r0g*H + c0 + 4] = ob;
        *(float4*)&g_h[r1g*H + c0]     = oc;
        *(float4*)&g_h[r1g*H + c0 + 4] = od;
    }
}

// ---------------------------------------------------------------------------
__global__ void k_fc2sort(const float* __restrict__ fc2_w,
                          const float* __restrict__ fc2_b,
                          float* __restrict__ out) {
    __shared__ float hq[H*NQ];
    __shared__ float sq[NA*NQ];
    int b = blockIdx.x;
    int g = b >> 3;
    int t = threadIdx.x;
    for (int i = t; i < H*NQ; i += 128) {
        int qi = i >> 7, j = i & 127;
        hq[j*NQ + qi] = g_h[b*H + j] * g_qphi[(g*NQ + qi)*H + j];
    }
    __syncthreads();
    if (t < NA*NQ) {
        int na = t >> 3, qi = t & 7;
        float acc = fc2_b[na];
        #pragma unroll 8
        for (int j = 0; j < H; j++)
            acc = fmaf(hq[j*NQ + qi], fc2_w[j*NA + na], acc);
        sq[na*NQ + qi] = acc;
    }
    __syncthreads();
    if (t < NA) {
        float v[NQ];
        #pragma unroll
        for (int k = 0; k < NQ; k++) v[k] = sq[t*NQ + k];
        #pragma unroll
        for (int i = 1; i < NQ; i++) {
            float key = v[i];
            int p = i - 1;
            while (p >= 0 && v[p] > key) { v[p+1] = v[p]; p--; }
            v[p+1] = key;
        }
        #pragma unroll
        for (int k = 0; k < NQ; k++)
            out[OFF_SQ + b*(NA*NQ) + t*NQ + k] = v[k];
    }
}

// ---------------------------------------------------------------------------
extern "C" void kernel_launch(void* const* d_in, const int* in_sizes, int n_in,
                              void* d_out, int out_size) {
    const float* in        = (const float*)d_in[0];
    const float* hidden    = (const float*)d_in[1];
    const float* rqs       = (const float*)d_in[2];
    const float* fc1_w     = (const float*)d_in[3];
    const float* fc1_b     = (const float*)d_in[4];
    const float* hyp_w1    = (const float*)d_in[5];
    const float* hyp_b1    = (const float*)d_in[6];
    const float* hyp_w2    = (const float*)d_in[7];
    const float* hyp_b2    = (const float*)d_in[8];
    const float* merger_w  = (const float*)d_in[9];
    const float* gru_wi    = (const float*)d_in[10];
    const float* gru_wh    = (const float*)d_in[11];
    const float* gru_bi    = (const float*)d_in[12];
    const float* gru_bh    = (const float*)d_in[13];
    const float* phi_w     = (const float*)d_in[14];
    const float* phi_b     = (const float*)d_in[15];
    const float* fc2_w     = (const float*)d_in[16];
    const float* fc2_b     = (const float*)d_in[17];
    float* out = (float*)d_out;

    static int smem_set = 0;
    if (!smem_set) {
        cudaFuncSetAttribute(k_main, cudaFuncAttributeMaxDynamicSharedMemorySize,
                             SMEM_BYTES);
        smem_set = 1;
    }

    k_wprep<<<1025 + BSG*NQ, 128>>>(hyp_w1, hyp_b1, hyp_w2, hyp_b2, merger_w,
                                    gru_wi, gru_wh, rqs, phi_w, phi_b, out);
    k_main<<<BS/32, 256, SMEM_BYTES>>>(in, hidden, fc1_w, fc1_b, gru_bi, gru_bh, out);
    k_fc2sort<<<BS, 128>>>(fc2_w, fc2_b, out);
}

// round 6
// speedup vs baseline: 1.8056x; 1.2538x over previous
#include <cuda_runtime.h>
#include <math.h>

// dims
#define E    256
#define H    128
#define NQ   8
#define QED  64
#define HYP  64
#define NA   14
#define NAG  8
#define BS   4096
#define BSG  512
#define WSZ  32768

// output layout: sorted_q [BS,NA,NQ] | h [BS,H] | rq [BSG,NQ]
#define OFF_SQ 0
#define OFF_H  (BS*NA*NQ)
#define OFF_RQ (OFF_H + BS*H)

// scratch
__device__ __align__(16) float g_msm[2*H];
__device__ __align__(16) float g_W[H*2*H];        // [128][256]
__device__ __align__(16) float g_wrz[2*H*2*H];    // [256][256]
__device__ __align__(16) float g_wn[H*2*H];       // [128][256]
__device__ __align__(16) float g_qphi[BSG*NQ*H];

typedef unsigned long long u64t;
__device__ __forceinline__ u64t pk2(float a) {
    u64t r; asm("mov.b64 %0, {%1,%1};" : "=l"(r) : "f"(a)); return r;
}
__device__ __forceinline__ u64t pk2b(float a, float b) {
    u64t r; asm("mov.b64 %0, {%1,%2};" : "=l"(r) : "f"(a), "f"(b)); return r;
}
__device__ __forceinline__ void fma2(u64t& d, u64t a, u64t b) {
    asm("fma.rn.f32x2 %0, %1, %2, %3;" : "=l"(d) : "l"(a), "l"(b), "l"(d));
}
__device__ __forceinline__ float2 upk(u64t v) {
    float2 f; asm("mov.b64 {%0,%1}, %2;" : "=f"(f.x), "=f"(f.y) : "l"(v)); return f;
}
__device__ __forceinline__ float sigm(float x) {
    return __fdividef(1.f, 1.f + __expf(-x));
}

// cp.async helpers
__device__ __forceinline__ void cpa16(unsigned s, const void* g) {
    asm volatile("cp.async.cg.shared.global [%0], [%1], 16;" :: "r"(s), "l"(g));
}
__device__ __forceinline__ void cpcommit() { asm volatile("cp.async.commit_group;"); }
__device__ __forceinline__ void cpwait1()  { asm volatile("cp.async.wait_group 1;"); }
__device__ __forceinline__ void cpwait0()  { asm volatile("cp.async.wait_group 0;"); }

// ---------------------------------------------------------------------------
// merged weight-prep + qphi kernel. 256 threads/block.
// blocks [0,128): buildW ; [128,384): g_wrz (256 blk x 256 thr = 65536)
// [384,512): g_wn (128 x 256 = 32768) ; 512: msm ; [513, 513+4096): qphi
__global__ __launch_bounds__(256)
void k_wprep(const float* __restrict__ hyp_w1,
             const float* __restrict__ hyp_b1,
             const float* __restrict__ hyp_w2,
             const float* __restrict__ hyp_b2,
             const float* __restrict__ merger_w,
             const float* __restrict__ gwi,
             const float* __restrict__ gwh,
             const float* __restrict__ rq,
             const float* __restrict__ phi_w,
             const float* __restrict__ phi_b,
             float* __restrict__ out) {
    int bid = blockIdx.x, t = threadIdx.x;
    if (bid < 128) {
        __shared__ float sh[HYP];
        __shared__ float4 sred[256];
        if (t < HYP) {
            float s = hyp_b1[t];
            #pragma unroll
            for (int q = 0; q < NQ; q++) s += hyp_w1[q*HYP + t];
            sh[t] = fmaxf(s, 0.f);
        }
        __syncthreads();
        int m4loc = t & 63, fc = t >> 6;        // fc 0..3
        int m4 = bid*64 + m4loc;                // 0..8191 (float4 cols)
        const float4* src = (const float4*)hyp_w2;
        float4 acc = make_float4(0.f, 0.f, 0.f, 0.f);
        #pragma unroll
        for (int f = 0; f < 16; f++) {
            float s = sh[fc*16 + f];
            float4 v = src[(fc*16 + f)*8192 + m4];
            acc.x = fmaf(s, v.x, acc.x);
            acc.y = fmaf(s, v.y, acc.y);
            acc.z = fmaf(s, v.z, acc.z);
            acc.w = fmaf(s, v.w, acc.w);
        }
        sred[t] = acc;
        __syncthreads();
        if (fc == 0) {
            float4 a = sred[t], b = sred[t+64], c = sred[t+128], d = sred[t+192];
            float4 bi = ((const float4*)hyp_b2)[m4];
            float4 r;
            r.x = a.x + b.x + c.x + d.x + bi.x;
            r.y = a.y + b.y + c.y + d.y + bi.y;
            r.z = a.z + b.z + c.z + d.z + bi.z;
            r.w = a.w + b.w + c.w + d.w + bi.w;
            ((float4*)g_W)[m4] = r;
        }
    } else if (bid < 384) {
        int idx = (bid - 128)*256 + t;     // 0..65535
        int k = idx >> 8, j = idx & 255;
        g_wrz[idx] = (k < 128) ? gwi[j*128 + k] : gwh[j*128 + (k - 128)];
    } else if (bid < 512) {
        int idx = (bid - 384)*256 + t;     // 0..32767
        int k = idx >> 8, j = idx & 255;
        g_wn[idx] = (j < 128) ? gwi[(256 + j)*128 + k] : gwh[(128 + j)*128 + k];
    } else if (bid == 512) {
        if (t < H) {
            float a = merger_w[t], b = merger_w[H + t];
            float m = fmaxf(a, b);
            float e0 = expf(a - m), e1 = expf(b - m);
            float inv = 1.f / (e0 + e1);
            g_msm[t]     = e0 * inv;
            g_msm[H + t] = e1 * inv;
        }
    } else {
        __shared__ float c[QED];
        int r = bid - 513;                 // 0..4095
        float rqv = rq[r];
        if (t < QED) c[t] = cospif((float)t * rqv);
        if (t == 0) out[OFF_RQ + r] = rqv;
        __syncthreads();
        if (t < H) {
            float acc = phi_b[t];
            #pragma unroll 8
            for (int f = 0; f < QED; f++) acc = fmaf(c[f], phi_w[f*H + t], acc);
            g_qphi[r*H + t] = fmaxf(acc, 0.f);
        }
    }
}

// ---------------------------------------------------------------------------
// fused main: fc1 -> emb -> merge -> GRU -> fc2 -> sort.
// 256 threads, 32 rows/block, 128 blocks.
#define SC_STR 257
#define SX_STR 129
#define SC_F (32*SC_STR)
#define SX_F (32*SX_STR)
#define SB_F (3*4096)
#define SMEM_BYTES ((SC_F + SX_F + SB_F)*4)

__device__ __forceinline__ void stage16k(unsigned sbu, int bufi,
                                         const float* src, int tid) {
    unsigned d = sbu + (unsigned)(bufi*16384 + tid*16);
    const char* s = (const char*)src + tid*16;
    #pragma unroll
    for (int i = 0; i < 4; i++) cpa16(d + i*4096, s + i*4096);
}

__global__ __launch_bounds__(256, 1)
void k_main(const float* __restrict__ in, const float* __restrict__ hprev,
            const float* __restrict__ fc1_w, const float* __restrict__ fc1_b,
            const float* __restrict__ gbi,  const float* __restrict__ gbh,
            const float* __restrict__ fc2_w, const float* __restrict__ fc2_b,
            float* __restrict__ out) {
    extern __shared__ float smem[];
    float* sC = smem;
    float* sX = smem + SC_F;
    float* sB = smem + SC_F + SX_F;
    unsigned sbu = (unsigned)__cvta_generic_to_shared(sB);

    const int tid  = threadIdx.x;
    const int lane = tid & 31;
    const int warp = tid >> 5;              // 0..7
    const int rowA = lane & 15;
    const int c0   = warp*16 + (lane >> 4)*8;
    const int row0 = blockIdx.x * 32;

    // stage input A [32][256] -> sC
    {
        const float4* src = (const float4*)(in + row0*E);
        #pragma unroll
        for (int i = tid; i < 2048; i += 256) {
            float4 v = src[i];
            int f = i * 4;
            int r = f >> 8, cc = f & 255;
            float* p = sC + r*SC_STR + cc;
            p[0] = v.x; p[1] = v.y; p[2] = v.z; p[3] = v.w;
        }
    }
    stage16k(sbu, 0, fc1_w, tid); cpcommit();

    // ======== FC1 : tiles g=0..7, KT=32, width 128 ========
    u64t X0[4], X1[4];
    {
        float4 b0 = *(const float4*)(fc1_b + c0);
        float4 b1 = *(const float4*)(fc1_b + c0 + 4);
        X0[0] = pk2b(b0.x, b0.y); X0[1] = pk2b(b0.z, b0.w);
        X0[2] = pk2b(b1.x, b1.y); X0[3] = pk2b(b1.z, b1.w);
        X1[0] = X0[0]; X1[1] = X0[1]; X1[2] = X0[2]; X1[3] = X0[3];
    }
    #pragma unroll 1
    for (int t = 0; t < 8; t++) {
        int g = t;
        const float* nsrc = (t < 7) ? (fc1_w + (t+1)*4096) : g_W;
        stage16k(sbu, (g+1)%3, nsrc, tid); cpcommit();
        cpwait1();
        __syncthreads();
        const float* bw  = sB + (g%3)*4096;
        const float* a0p = sC + rowA*SC_STR + t*32;
        const float* a1p = a0p + 16*SC_STR;
        #pragma unroll 8
        for (int kk = 0; kk < 32; kk++) {
            const float* wr = bw + kk*128 + c0;
            ulonglong2 w01 = *(const ulonglong2*)wr;
            ulonglong2 w23 = *(const ulonglong2*)(wr + 4);
            u64t a0 = pk2(a0p[kk]);
            u64t a1 = pk2(a1p[kk]);
            fma2(X0[0], a0, w01.x); fma2(X0[1], a0, w01.y);
            fma2(X0[2], a0, w23.x); fma2(X0[3], a0, w23.y);
            fma2(X1[0], a1, w01.x); fma2(X1[1], a1, w01.y);
            fma2(X1[2], a1, w23.x); fma2(X1[3], a1, w23.y);
        }
    }
    {
        float* xo0 = sX + rowA*SX_STR + c0;
        float* xo1 = xo0 + 16*SX_STR;
        #pragma unroll
        for (int cc = 0; cc < 4; cc++) {
            float2 v0 = upk(X0[cc]);
            float2 v1 = upk(X1[cc]);
            xo0[2*cc]   = fmaxf(v0.x, 0.f); xo0[2*cc+1] = fmaxf(v0.y, 0.f);
            xo1[2*cc]   = fmaxf(v1.x, 0.f); xo1[2*cc+1] = fmaxf(v1.y, 0.f);
        }
    }

    // ======== EMB : tiles g=8..15, KT=16, width 256 ========
    u64t P0[4] = {0,0,0,0}, P1[4] = {0,0,0,0};
    u64t Q0[4] = {0,0,0,0}, Q1[4] = {0,0,0,0};
    #pragma unroll 1
    for (int t = 0; t < 8; t++) {
        int g = 8 + t;
        const float* nsrc = (t < 7) ? (g_W + (t+1)*4096) : g_wrz;
        stage16k(sbu, (g+1)%3, nsrc, tid); cpcommit();
        cpwait1();
        __syncthreads();
        const float* bw  = sB + (g%3)*4096;
        const float* a0p = sX + rowA*SX_STR + t*16;
        const float* a1p = a0p + 16*SX_STR;
        #pragma unroll 4
        for (int kk = 0; kk < 16; kk++) {
            const float* wr0 = bw + kk*256 + c0;
            ulonglong2 p01 = *(const ulonglong2*)wr0;
            ulonglong2 p23 = *(const ulonglong2*)(wr0 + 4);
            ulonglong2 q01 = *(const ulonglong2*)(wr0 + 128);
            ulonglong2 q23 = *(const ulonglong2*)(wr0 + 132);
            u64t a0 = pk2(a0p[kk]);
            u64t a1 = pk2(a1p[kk]);
            fma2(P0[0], a0, p01.x); fma2(P0[1], a0, p01.y);
            fma2(P0[2], a0, p23.x); fma2(P0[3], a0, p23.y);
            fma2(P1[0], a1, p01.x); fma2(P1[1], a1, p01.y);
            fma2(P1[2], a1, p23.x); fma2(P1[3], a1, p23.y);
            fma2(Q0[0], a0, q01.x); fma2(Q0[1], a0, q01.y);
            fma2(Q0[2], a0, q23.x); fma2(Q0[3], a0, q23.y);
            fma2(Q1[0], a1, q01.x); fma2(Q1[1], a1, q01.y);
            fma2(Q1[2], a1, q23.x); fma2(Q1[3], a1, q23.y);
        }
    }

    // ---- merge + relu -> x2 into sC[0,128); stage hprev -> sC[128,256)
    {
        float4 m0a = *(const float4*)(g_msm + c0);
        float4 m0b = *(const float4*)(g_msm + c0 + 4);
        float4 m1a = *(const float4*)(g_msm + H + c0);
        float4 m1b = *(const float4*)(g_msm + H + c0 + 4);
        float m0v[8] = {m0a.x,m0a.y,m0a.z,m0a.w,m0b.x,m0b.y,m0b.z,m0b.w};
        float m1v[8] = {m1a.x,m1a.y,m1a.z,m1a.w,m1b.x,m1b.y,m1b.z,m1b.w};
        float* co0 = sC + rowA*SC_STR + c0;
        float* co1 = co0 + 16*SC_STR;
        #pragma unroll
        for (int cc = 0; cc < 4; cc++) {
            float2 a0 = upk(P0[cc]); float2 b0 = upk(Q0[cc]);
            float2 a1 = upk(P1[cc]); float2 b1 = upk(Q1[cc]);
            co0[2*cc]   = fmaxf(fmaf(m0v[2*cc],   a0.x, m1v[2*cc]  *b0.x), 0.f);
            co0[2*cc+1] = fmaxf(fmaf(m0v[2*cc+1], a0.y, m1v[2*cc+1]*b0.y), 0.f);
            co1[2*cc]   = fmaxf(fmaf(m0v[2*cc],   a1.x, m1v[2*cc]  *b1.x), 0.f);
            co1[2*cc+1] = fmaxf(fmaf(m0v[2*cc+1], a1.y, m1v[2*cc+1]*b1.y), 0.f);
        }
        const float4* hsrc = (const float4*)(hprev + row0*H);
        #pragma unroll
        for (int i = tid; i < 1024; i += 256) {
            float4 v = hsrc[i];
            int f = i * 4;
            int r = f >> 7, cc = f & 127;
            float* p = sC + r*SC_STR + 128 + cc;
            p[0] = v.x; p[1] = v.y; p[2] = v.z; p[3] = v.w;
        }
    }

    // ======== GRU r,z : tiles g=16..31 ========
    float rs[2][8], zs[2][8];
    {
        u64t R0[4], R1[4], Z0[4], Z1[4];
        {
            float4 bi0 = *(const float4*)(gbi + c0);
            float4 bi1 = *(const float4*)(gbi + c0 + 4);
            float4 bh0 = *(const float4*)(gbh + c0);
            float4 bh1 = *(const float4*)(gbh + c0 + 4);
            R0[0] = pk2b(bi0.x+bh0.x, bi0.y+bh0.y);
            R0[1] = pk2b(bi0.z+bh0.z, bi0.w+bh0.w);
            R0[2] = pk2b(bi1.x+bh1.x, bi1.y+bh1.y);
            R0[3] = pk2b(bi1.z+bh1.z, bi1.w+bh1.w);
            float4 ci0 = *(const float4*)(gbi + H + c0);
            float4 ci1 = *(const float4*)(gbi + H + c0 + 4);
            float4 ch0 = *(const float4*)(gbh + H + c0);
            float4 ch1 = *(const float4*)(gbh + H + c0 + 4);
            Z0[0] = pk2b(ci0.x+ch0.x, ci0.y+ch0.y);
            Z0[1] = pk2b(ci0.z+ch0.z, ci0.w+ch0.w);
            Z0[2] = pk2b(ci1.x+ch1.x, ci1.y+ch1.y);
            Z0[3] = pk2b(ci1.z+ch1.z, ci1.w+ch1.w);
            #pragma unroll
            for (int i = 0; i < 4; i++) { R1[i] = R0[i]; Z1[i] = Z0[i]; }
        }
        #pragma unroll 1
        for (int t = 0; t < 16; t++) {
            int g = 16 + t;
            const float* nsrc = (t < 15) ? (g_wrz + (t+1)*4096) : g_wn;
            stage16k(sbu, (g+1)%3, nsrc, tid); cpcommit();
            cpwait1();
            __syncthreads();
            const float* bw  = sB + (g%3)*4096;
            const float* a0p = sC + rowA*SC_STR + t*16;
            const float* a1p = a0p + 16*SC_STR;
            #pragma unroll 4
            for (int kk = 0; kk < 16; kk++) {
                const float* wr0 = bw + kk*256 + c0;
                ulonglong2 p01 = *(const ulonglong2*)wr0;
                ulonglong2 p23 = *(const ulonglong2*)(wr0 + 4);
                ulonglong2 q01 = *(const ulonglong2*)(wr0 + 128);
                ulonglong2 q23 = *(const ulonglong2*)(wr0 + 132);
                u64t a0 = pk2(a0p[kk]);
                u64t a1 = pk2(a1p[kk]);
                fma2(R0[0], a0, p01.x); fma2(R0[1], a0, p01.y);
                fma2(R0[2], a0, p23.x); fma2(R0[3], a0, p23.y);
                fma2(R1[0], a1, p01.x); fma2(R1[1], a1, p01.y);
                fma2(R1[2], a1, p23.x); fma2(R1[3], a1, p23.y);
                fma2(Z0[0], a0, q01.x); fma2(Z0[1], a0, q01.y);
                fma2(Z0[2], a0, q23.x); fma2(Z0[3], a0, q23.y);
                fma2(Z1[0], a1, q01.x); fma2(Z1[1], a1, q01.y);
                fma2(Z1[2], a1, q23.x); fma2(Z1[3], a1, q23.y);
            }
        }
        #pragma unroll
        for (int cc = 0; cc < 4; cc++) {
            float2 r0 = upk(R0[cc]); float2 r1 = upk(R1[cc]);
            float2 z0 = upk(Z0[cc]); float2 z1 = upk(Z1[cc]);
            rs[0][2*cc] = sigm(r0.x); rs[0][2*cc+1] = sigm(r0.y);
            rs[1][2*cc] = sigm(r1.x); rs[1][2*cc+1] = sigm(r1.y);
            zs[0][2*cc] = sigm(z0.x); zs[0][2*cc+1] = sigm(z0.y);
            zs[1][2*cc] = sigm(z1.x); zs[1][2*cc+1] = sigm(z1.y);
        }
    }

    // ======== GRU n : tiles g=32..39 ========
    {
        u64t N0[4], N1[4], G0[4], G1[4];
        {
            float4 ni0 = *(const float4*)(gbi + 2*H + c0);
            float4 ni1 = *(const float4*)(gbi + 2*H + c0 + 4);
            float4 nh0 = *(const float4*)(gbh + 2*H + c0);
            float4 nh1 = *(const float4*)(gbh + 2*H + c0 + 4);
            N0[0] = pk2b(ni0.x, ni0.y); N0[1] = pk2b(ni0.z, ni0.w);
            N0[2] = pk2b(ni1.x, ni1.y); N0[3] = pk2b(ni1.z, ni1.w);
            G0[0] = pk2b(nh0.x, nh0.y); G0[1] = pk2b(nh0.z, nh0.w);
            G0[2] = pk2b(nh1.x, nh1.y); G0[3] = pk2b(nh1.z, nh1.w);
            #pragma unroll
            for (int i = 0; i < 4; i++) { N1[i] = N0[i]; G1[i] = G0[i]; }
        }
        #pragma unroll 1
        for (int t = 0; t < 8; t++) {
            int g = 32 + t;
            if (t < 7) { stage16k(sbu, (g+1)%3, g_wn + (t+1)*4096, tid); cpcommit(); cpwait1(); }
            else cpwait0();
            __syncthreads();
            const float* bw  = sB + (g%3)*4096;
            const float* a0p = sC + rowA*SC_STR + t*16;
            const float* a1p = a0p + 16*SC_STR;
            #pragma unroll 4
            for (int kk = 0; kk < 16; kk++) {
                const float* wr0 = bw + kk*256 + c0;
                ulonglong2 p01 = *(const ulonglong2*)wr0;
                ulonglong2 p23 = *(const ulonglong2*)(wr0 + 4);
                ulonglong2 q01 = *(const ulonglong2*)(wr0 + 128);
                ulonglong2 q23 = *(const ulonglong2*)(wr0 + 132);
                u64t x0 = pk2(a0p[kk]);
                u64t x1 = pk2(a1p[kk]);
                u64t h0 = pk2(a0p[kk + 128]);
                u64t h1 = pk2(a1p[kk + 128]);
                fma2(N0[0], x0, p01.x); fma2(N0[1], x0, p01.y);
                fma2(N0[2], x0, p23.x); fma2(N0[3], x0, p23.y);
                fma2(N1[0], x1, p01.x); fma2(N1[1], x1, p01.y);
                fma2(N1[2], x1, p23.x); fma2(N1[3], x1, p23.y);
                fma2(G0[0], h0, q01.x); fma2(G0[1], h0, q01.y);
                fma2(G0[2], h0, q23.x); fma2(G0[3], h0, q23.y);
                fma2(G1[0], h1, q01.x); fma2(G1[1], h1, q01.y);
                fma2(G1[2], h1, q23.x); fma2(G1[3], h1, q23.y);
            }
        }

        // finalize h
        float hv0[8], hv1[8];
        const float* hp0 = sC + rowA*SC_STR + 128 + c0;
        const float* hp1 = hp0 + 16*SC_STR;
        #pragma unroll
        for (int cc = 0; cc < 4; cc++) {
            float2 nv0 = upk(N0[cc]); float2 gv0 = upk(G0[cc]);
            float2 nv1 = upk(N1[cc]); float2 gv1 = upk(G1[cc]);
            float n00 = tanhf(fmaf(rs[0][2*cc],   gv0.x, nv0.x));
            float n01 = tanhf(fmaf(rs[0][2*cc+1], gv0.y, nv0.y));
            float n10 = tanhf(fmaf(rs[1][2*cc],   gv1.x, nv1.x));
            float n11 = tanhf(fmaf(rs[1][2*cc+1], gv1.y, nv1.y));
            hv0[2*cc]   = (1.f - zs[0][2*cc])  * n00 + zs[0][2*cc]  * hp0[2*cc];
            hv0[2*cc+1] = (1.f - zs[0][2*cc+1])* n01 + zs[0][2*cc+1]* hp0[2*cc+1];
            hv1[2*cc]   = (1.f - zs[1][2*cc])  * n10 + zs[1][2*cc]  * hp1[2*cc];
            hv1[2*cc+1] = (1.f - zs[1][2*cc+1])* n11 + zs[1][2*cc+1]* hp1[2*cc+1];
        }
        int r0g = row0 + rowA, r1g = r0g + 16;
        *(float4*)&out[OFF_H + r0g*H + c0]     = make_float4(hv0[0], hv0[1], hv0[2], hv0[3]);
        *(float4*)&out[OFF_H + r0g*H + c0 + 4] = make_float4(hv0[4], hv0[5], hv0[6], hv0[7]);
        *(float4*)&out[OFF_H + r1g*H + c0]     = make_float4(hv1[0], hv1[1], hv1[2], hv1[3]);
        *(float4*)&out[OFF_H + r1g*H + c0 + 4] = make_float4(hv1[4], hv1[5], hv1[6], hv1[7]);

        __syncthreads();           // everyone done reading sC (x2/hp)

        // write h into sC cols [0,128)
        float* ho0 = sC + rowA*SC_STR + c0;
        float* ho1 = ho0 + 16*SC_STR;
        #pragma unroll
        for (int cc = 0; cc < 8; cc++) { ho0[cc] = hv0[cc]; ho1[cc] = hv1[cc]; }
    }

    // ======== epilogue: fc2 + transpose + sort ========
    {
        float* sQ = sB;
        float* sW = sX;
        float* ssq = sB + 4224;
        #pragma unroll
        for (int i = tid; i < 4096; i += 256) {
            int qq = i >> 7, j = i & 127;
            sQ[qq*129 + j] = g_qphi[(row0 + qq)*H + j];
        }
        for (int i = tid; i < H*NA; i += 256) {
            int j = i / NA, na = i - j*NA;
            sW[j*16 + na] = fc2_w[i];
        }
        __syncthreads();

        const int row = tid & 31;        // local row
        const int qi  = tid >> 5;        // 0..7
        const float* hrow = sC + row*SC_STR;
        const float* qrow = sQ + ((row >> 3)*8 + qi)*129;
        u64t acc[7];
        #pragma unroll
        for (int p = 0; p < 7; p++) acc[p] = pk2b(fc2_b[2*p], fc2_b[2*p+1]);
        #pragma unroll 4
        for (int j = 0; j < H; j++) {
            float hq = hrow[j] * qrow[j];
            u64t h2 = pk2(hq);
            const ulonglong2* wp = (const ulonglong2*)(sW + j*16);
            ulonglong2 w0 = wp[0], w1 = wp[1];
            u64t w2 = *(const u64t*)(sW + j*16 + 8);
            u64t w3 = *(const u64t*)(sW + j*16 + 10);
            u64t w4 = *(const u64t*)(sW + j*16 + 12);
            fma2(acc[0], h2, w0.x); fma2(acc[1], h2, w0.y);
            fma2(acc[2], h2, w1.x); fma2(acc[3], h2, w1.y);
            fma2(acc[4], h2, w2);   fma2(acc[5], h2, w3);
            fma2(acc[6], h2, w4);
        }
        #pragma unroll
        for (int p = 0; p < 7; p++) {
            float2 v = upk(acc[p]);
            ssq[row*112 + (2*p)*8   + qi] = v.x;
            ssq[row*112 + (2*p+1)*8 + qi] = v.y;
        }
        __syncthreads();

        // sort: 448 (row,na) pairs
        for (int p = tid; p < 448; p += 256) {
            int r = p / NA, na = p - r*NA;
            const float* s = ssq + r*112 + na*8;
            float v[NQ];
            #pragma unroll
            for (int k = 0; k < NQ; k++) v[k] = s[k];
            #pragma unroll
            for (int i = 1; i < NQ; i++) {
                float key = v[i];
                int q = i - 1;
                while (q >= 0 && v[q] > key) { v[q+1] = v[q]; q--; }
                v[q+1] = key;
            }
            float* o = out + OFF_SQ + (row0 + r)*112 + na*8;
            *(float4*)o       = make_float4(v[0], v[1], v[2], v[3]);
            *(float4*)(o + 4) = make_float4(v[4], v[5], v[6], v[7]);
        }
    }
}

// ---------------------------------------------------------------------------
extern "C" void kernel_launch(void* const* d_in, const int* in_sizes, int n_in,
                              void* d_out, int out_size) {
    const float* in        = (const float*)d_in[0];
    const float* hidden    = (const float*)d_in[1];
    const float* rqs       = (const float*)d_in[2];
    const float* fc1_w     = (const float*)d_in[3];
    const float* fc1_b     = (const float*)d_in[4];
    const float* hyp_w1    = (const float*)d_in[5];
    const float* hyp_b1    = (const float*)d_in[6];
    const float* hyp_w2    = (const float*)d_in[7];
    const float* hyp_b2    = (const float*)d_in[8];
    const float* merger_w  = (const float*)d_in[9];
    const float* gru_wi    = (const float*)d_in[10];
    const float* gru_wh    = (const float*)d_in[11];
    const float* gru_bi    = (const float*)d_in[12];
    const float* gru_bh    = (const float*)d_in[13];
    const float* phi_w     = (const float*)d_in[14];
    const float* phi_b     = (const float*)d_in[15];
    const float* fc2_w     = (const float*)d_in[16];
    const float* fc2_b     = (const float*)d_in[17];
    float* out = (float*)d_out;

    static int smem_set = 0;
    if (!smem_set) {
        cudaFuncSetAttribute(k_main, cudaFuncAttributeMaxDynamicSharedMemorySize,
                             SMEM_BYTES);
        smem_set = 1;
    }

    k_wprep<<<513 + BSG*NQ, 256>>>(hyp_w1, hyp_b1, hyp_w2, hyp_b2, merger_w,
                                   gru_wi, gru_wh, rqs, phi_w, phi_b, out);
    k_main<<<BS/32, 256, SMEM_BYTES>>>(in, hidden, fc1_w, fc1_b, gru_bi, gru_bh,
                                       fc2_w, fc2_b, out);
}